// round 9
// baseline (speedup 1.0000x reference)
#include <cuda_runtime.h>

#define NLAB 21
#define BB   64
#define TT   512
#define DD   1024
#define ROWS (BB*TT)
#define LOGITS_N  (ROWS*NLAB)
#define LOSS_IDX  LOGITS_N
#define TAGS_BASE (LOGITS_N+1)
#define FULLMASK 0xffffffffu
#define NEG_BIG  (-1e30f)

typedef unsigned long long ull;
__device__ __forceinline__ ull fma2(ull a, ull b, ull c) {
    ull d; asm("fma.rn.f32x2 %0, %1, %2, %3;" : "=l"(d) : "l"(a), "l"(b), "l"(c));
    return d;
}
union F4U { float4 f; ull u[2]; };
union F2U { ull u; float2 f; };

__device__ float g_alpha[BB * TT * 24];
__device__ int   g_lasttag[BB];

// ---------------------------------------------------------------------------
// GEMM: logits = mlm @ W^T + b. 512 blocks x 64 threads, 64 rows/block,
// 1 row/thread. X staged transposed (pitch 65 f4, conflict-free), register
// prefetch. High block count -> ~7 warps/SM -> HBM + fma latency hidden.
// ---------------------------------------------------------------------------
#define GP4 65
__global__ __launch_bounds__(64)
void gemm_kernel(const float* __restrict__ mlm, const float* __restrict__ W,
                 const float* __restrict__ bias, float* out)
{
    __shared__ float4 Xs4[8 * GP4];      // 8320 B
    __shared__ float4 Wq4[NLAB * 8];     // 2688 B
    __shared__ float  bias_s[NLAB];

    const int tid = threadIdx.x;
    const int R0  = blockIdx.x * 64;
    const int row = R0 + tid;
    if (blockIdx.x == 0 && tid == 0) out[LOSS_IDX] = 0.0f;
    if (tid < NLAB) bias_s[tid] = bias[tid];

    const int kc  = tid & 7;    // f4 slot within k-tile
    const int rlb = tid >> 3;   // base row (0..7), rows rlb+8*i

    ull acc[NLAB];
#pragma unroll
    for (int j = 0; j < NLAB; j++) acc[j] = 0ull;

    const float4* mlm4 = (const float4*)mlm;
    const float4* W4   = (const float4*)W;

    float4 nv[8], nw[3];
#pragma unroll
    for (int i = 0; i < 8; i++)
        nv[i] = mlm4[(size_t)(R0 + rlb + 8 * i) * 256 + kc];
#pragma unroll
    for (int p = 0; p < 3; p++) {
        int w = tid + 64 * p;
        nw[p] = (w < NLAB * 8) ? W4[(w >> 3) * 256 + (w & 7)]
                               : make_float4(0, 0, 0, 0);
    }
#pragma unroll
    for (int i = 0; i < 8; i++) Xs4[kc * GP4 + rlb + 8 * i] = nv[i];
#pragma unroll
    for (int p = 0; p < 3; p++) {
        int w = tid + 64 * p;
        if (w < NLAB * 8) Wq4[w] = nw[p];
    }
    __syncthreads();

#pragma unroll 1
    for (int tile = 0; tile < 32; tile++) {
        if (tile < 31) {
            const int tb = (tile + 1) * 8;
#pragma unroll
            for (int i = 0; i < 8; i++)
                nv[i] = mlm4[(size_t)(R0 + rlb + 8 * i) * 256 + tb + kc];
#pragma unroll
            for (int p = 0; p < 3; p++) {
                int w = tid + 64 * p;
                if (w < NLAB * 8) nw[p] = W4[(w >> 3) * 256 + tb + (w & 7)];
            }
        }
#pragma unroll
        for (int kq = 0; kq < 8; kq++) {
            F4U x; x.f = Xs4[kq * GP4 + tid];
#pragma unroll
            for (int j = 0; j < NLAB; j++) {
                F4U w; w.f = Wq4[j * 8 + kq];
                acc[j] = fma2(x.u[0], w.u[0], acc[j]);
                acc[j] = fma2(x.u[1], w.u[1], acc[j]);
            }
        }
        __syncthreads();
        if (tile < 31) {
#pragma unroll
            for (int i = 0; i < 8; i++) Xs4[kc * GP4 + rlb + 8 * i] = nv[i];
#pragma unroll
            for (int p = 0; p < 3; p++) {
                int w = tid + 64 * p;
                if (w < NLAB * 8) Wq4[w] = nw[p];
            }
        }
        __syncthreads();
    }

#pragma unroll
    for (int j = 0; j < NLAB; j++) {
        F2U a; a.u = acc[j];
        out[(size_t)row * NLAB + j] = a.f.x + a.f.y + bias_s[j];
    }
}

// ---------------------------------------------------------------------------
// k2 chains: grid 160 x 64. 0-63 fwd, 64-127 viterbi (alphas->gmem),
// 128-159 joint score. Branchless inner steps, renorm every step (fwd).
// ---------------------------------------------------------------------------
__global__ __launch_bounds__(64)
void crf_chain(const float* logits, const int* __restrict__ gold,
               const float* __restrict__ trans, const float* __restrict__ startT,
               const float* __restrict__ endT, float* out)
{
    __shared__ float em[2][64 * NLAB];
    __shared__ float abuf[2][65][24];

    const int bid  = blockIdx.x;
    const int tid  = threadIdx.x;
    const int warp = tid >> 5;
    const int lane = tid & 31;
    const int j    = (lane < NLAB) ? lane : (NLAB - 1);

    if (bid >= 128) {   // joint score
        const int b = (bid - 128) * 2 + warp;
        const float* lg = logits + (size_t)b * TT * NLAB;
        const int*   gb = gold + b * TT;
        float jp = 0.0f;
#pragma unroll 4
        for (int t = lane; t < TT; t += 32) {
            int g = gb[t];
            jp += lg[t * NLAB + g];
            if (t == 0)     jp += startT[g];
            if (t < TT - 1) jp += trans[g * NLAB + gb[t + 1]];
            else            jp += endT[g];
        }
#pragma unroll
        for (int w = 16; w; w >>= 1) jp += __shfl_xor_sync(FULLMASK, jp, w);
        if (lane == 0) atomicAdd(&out[LOSS_IDX], -jp);
        return;
    }

    const bool is_fwd = (bid < 64);
    const int  b      = is_fwd ? bid : (bid - 64);
    const float* lg   = logits + (size_t)b * TT * NLAB;

    float col[NLAB], st_init = 0.0f;
    if (warp == 0) {
        if (is_fwd) {
#pragma unroll
            for (int i = 0; i < NLAB; i++)
                col[i] = (lane < NLAB) ? __expf(trans[i * NLAB + j]) : 0.0f;
            st_init = (lane < NLAB) ? __expf(startT[j]) : 0.0f;
        } else {
#pragma unroll
            for (int i = 0; i < NLAB; i++) col[i] = trans[i * NLAB + j];
            st_init = startT[j];
        }
    }
    if (warp == 1) {
        if (is_fwd) for (int k = lane; k < 64 * NLAB; k += 32) em[0][k] = __expf(lg[k]);
        else        for (int k = lane; k < 64 * NLAB; k += 32) em[0][k] = lg[k];
    }
    __syncthreads();

    float st = 0.0f;
    int  eoff = 0;

    for (int it = 0; it < 9; it++) {
        if (warp == 0 && it < 8) {
            const int cb = it & 1;
            const float* e = em[cb];
            float* ab = &abuf[cb][0][0];
            if (lane < NLAB) ab[lane] = st;
            __syncwarp();

            if (is_fwd) {
                auto FS = [&](int s) {
                    const float* row = ab + s * 24;
                    float4 A0 = *(const float4*)(row);
                    float4 A1 = *(const float4*)(row + 4);
                    float4 A2 = *(const float4*)(row + 8);
                    float4 A3 = *(const float4*)(row + 12);
                    float4 A4 = *(const float4*)(row + 16);
                    float  a20 = row[20];
                    float  ev  = e[s * NLAB + j];
                    float u0 = A0.x*col[0]  + A1.w*col[7]  + A3.z*col[14];
                    float u1 = A0.y*col[1]  + A2.x*col[8]  + A3.w*col[15];
                    float u2 = A0.z*col[2]  + A2.y*col[9]  + A4.x*col[16];
                    float u3 = A0.w*col[3]  + A2.z*col[10] + A4.y*col[17];
                    float u4 = A1.x*col[4]  + A2.w*col[11] + A4.z*col[18];
                    float u5 = A1.y*col[5]  + A3.x*col[12] + A4.w*col[19];
                    float u6 = A1.z*col[6]  + A3.y*col[13] + a20*col[20];
                    float ns = (((u0 + u1) + (u2 + u3)) + ((u4 + u5) + u6)) * ev;
                    // exact power-of-2 renorm every step (branchless)
                    unsigned eb = __float_as_uint(A0.x) >> 23;
                    eoff += (int)eb - 127;
                    ns *= __uint_as_float((254u - eb) << 23);
                    st = ns;
                    if (lane < NLAB) ab[(s + 1) * 24 + lane] = ns;
                    __syncwarp();
                };
                if (it == 0) {
                    st = st_init * e[j];
                    if (lane < NLAB) ab[24 + lane] = st;
                    __syncwarp();
#pragma unroll 4
                    for (int s = 1; s < 64; s++) FS(s);
                } else {
#pragma unroll 4
                    for (int s = 0; s < 64; s++) FS(s);
                }
            } else {
                auto VS = [&](int s) {
                    const float* row = ab + s * 24;
                    float4 A0 = *(const float4*)(row);
                    float4 A1 = *(const float4*)(row + 4);
                    float4 A2 = *(const float4*)(row + 8);
                    float4 A3 = *(const float4*)(row + 12);
                    float4 A4 = *(const float4*)(row + 16);
                    float  a20 = row[20];
                    float  ev  = e[s * NLAB + j];
                    float v0  = A0.x + col[0],  v1  = A0.y + col[1];
                    float v2  = A0.z + col[2],  v3  = A0.w + col[3];
                    float v4  = A1.x + col[4],  v5  = A1.y + col[5];
                    float v6  = A1.z + col[6],  v7  = A1.w + col[7];
                    float v8  = A2.x + col[8],  v9  = A2.y + col[9];
                    float v10 = A2.z + col[10], v11 = A2.w + col[11];
                    float v12 = A3.x + col[12], v13 = A3.y + col[13];
                    float v14 = A3.z + col[14], v15 = A3.w + col[15];
                    float v16 = A4.x + col[16], v17 = A4.y + col[17];
                    float v18 = A4.z + col[18], v19 = A4.w + col[19];
                    float v20 = a20 + col[20];
                    float m0 = fmaxf(v0, v1),   m1 = fmaxf(v2, v3);
                    float m2 = fmaxf(v4, v5),   m3 = fmaxf(v6, v7);
                    float m4 = fmaxf(v8, v9),   m5 = fmaxf(v10, v11);
                    float m6 = fmaxf(v12, v13), m7 = fmaxf(v14, v15);
                    float m8 = fmaxf(v16, v17), m9 = fmaxf(v18, v19);
                    float n0 = fmaxf(m0, m1), n1 = fmaxf(m2, m3);
                    float n2 = fmaxf(m4, m5), n3 = fmaxf(m6, m7);
                    float n4 = fmaxf(m8, m9);
                    float ns = fmaxf(fmaxf(fmaxf(n0, n1), fmaxf(n2, n3)),
                                     fmaxf(n4, v20)) + ev;
                    st = ns;
                    if (lane < NLAB) ab[(s + 1) * 24 + lane] = ns;
                    __syncwarp();
                };
                if (it == 0) {
                    st = st_init + e[j];
                    if (lane < NLAB) ab[24 + lane] = st;
                    __syncwarp();
#pragma unroll 4
                    for (int s = 1; s < 64; s++) VS(s);
                } else {
#pragma unroll 4
                    for (int s = 0; s < 64; s++) VS(s);
                }
            }
        }
        if (warp == 1) {
            if (it < 7) {
                const float* src = lg + (it + 1) * 64 * NLAB;
                float* dst = em[(it + 1) & 1];
                if (is_fwd) for (int k = lane; k < 64 * NLAB; k += 32) dst[k] = __expf(src[k]);
                else        for (int k = lane; k < 64 * NLAB; k += 32) dst[k] = src[k];
            }
            if (!is_fwd && it >= 1) {
                const int c = it - 1;
                const float4* src = (const float4*)&abuf[c & 1][1][0];
                float4* dst = (float4*)(g_alpha + ((size_t)b * TT + c * 64) * 24);
#pragma unroll
                for (int k = 0; k < 12; k++) dst[lane + 32 * k] = src[lane + 32 * k];
            }
        }
        __syncthreads();
    }

    if (is_fwd) {
        if (warp == 0) {
            float val = (lane < NLAB) ? st * __expf(endT[j]) : 0.0f;
#pragma unroll
            for (int w = 16; w; w >>= 1) val += __shfl_xor_sync(FULLMASK, val, w);
            if (lane == 0)
                atomicAdd(&out[LOSS_IDX],
                          (float)eoff * 0.69314718055994531f + __logf(val));
        }
    } else if (warp == 0) {
        float v = (lane < NLAB) ? (st + endT[j]) : NEG_BIG;
        float m = v;
#pragma unroll
        for (int w = 16; w; w >>= 1) m = fmaxf(m, __shfl_xor_sync(FULLMASK, m, w));
        unsigned bal = __ballot_sync(FULLMASK, v == m);
        if (lane == 0) g_lasttag[b] = __ffs(bal) - 1;
    }
}

// ---------------------------------------------------------------------------
// argmax_i(Arow[i] + Tt[x][i]), lowest index wins
// ---------------------------------------------------------------------------
__device__ __forceinline__ int chase_step(const float4* A, float a20,
                                          const float* tr)
{
    float4 B0 = *(const float4*)(tr);
    float4 B1 = *(const float4*)(tr + 4);
    float4 B2 = *(const float4*)(tr + 8);
    float4 B3 = *(const float4*)(tr + 12);
    float4 B4 = *(const float4*)(tr + 16);
    float  b20 = tr[20];
    float v[21];
    v[0]=A[0].x+B0.x; v[1]=A[0].y+B0.y; v[2]=A[0].z+B0.z; v[3]=A[0].w+B0.w;
    v[4]=A[1].x+B1.x; v[5]=A[1].y+B1.y; v[6]=A[1].z+B1.z; v[7]=A[1].w+B1.w;
    v[8]=A[2].x+B2.x; v[9]=A[2].y+B2.y; v[10]=A[2].z+B2.z; v[11]=A[2].w+B2.w;
    v[12]=A[3].x+B3.x; v[13]=A[3].y+B3.y; v[14]=A[3].z+B3.z; v[15]=A[3].w+B3.w;
    v[16]=A[4].x+B4.x; v[17]=A[4].y+B4.y; v[18]=A[4].z+B4.z; v[19]=A[4].w+B4.w;
    v[20]=a20+b20;
    float m0 = fmaxf(v[0], v[1]),   m1 = fmaxf(v[2], v[3]);
    float m2 = fmaxf(v[4], v[5]),   m3 = fmaxf(v[6], v[7]);
    float m4 = fmaxf(v[8], v[9]),   m5 = fmaxf(v[10], v[11]);
    float m6 = fmaxf(v[12], v[13]), m7 = fmaxf(v[14], v[15]);
    float m8 = fmaxf(v[16], v[17]), m9 = fmaxf(v[18], v[19]);
    float best = fmaxf(fmaxf(fmaxf(fmaxf(m0, m1), fmaxf(m2, m3)),
                             fmaxf(fmaxf(m4, m5), fmaxf(m6, m7))),
                       fmaxf(fmaxf(m8, m9), v[20]));
    int idx = 20;
#pragma unroll
    for (int i = 19; i >= 0; i--) idx = (v[i] == best) ? i : idx;
    return idx;
}

// ---------------------------------------------------------------------------
// k3 finalize: 64 blocks x 256. warp = chunk, lane = exit tag; lane-parallel
// chases straight off g_alpha; stitch + write tags.
// ---------------------------------------------------------------------------
__global__ __launch_bounds__(256)
void crf_fin(const float* __restrict__ trans, float* out)
{
    __shared__ float         Tt[NLAB][24];
    __shared__ unsigned char pathbuf[8][NLAB][64];
    __shared__ unsigned char entry_s[8][NLAB];
    __shared__ int           sel[8];

    const int b    = blockIdx.x;
    const int tid  = threadIdx.x;
    const int c    = tid >> 5;
    const int lane = tid & 31;

    for (int k = tid; k < NLAB * NLAB; k += 256) {
        int i = k / NLAB, x = k - i * NLAB;
        Tt[x][i] = trans[k];
    }
    __syncthreads();

    if (lane < NLAB) {
        const int x0 = lane;
        const float* ab = g_alpha + (size_t)b * TT * 24;
        int cur = x0;
        pathbuf[c][x0][63] = (unsigned char)cur;

        const float* rw = ab + (c * 64 + 62) * 24;
        float4 A[5];
        A[0] = *(const float4*)(rw);      A[1] = *(const float4*)(rw + 4);
        A[2] = *(const float4*)(rw + 8);  A[3] = *(const float4*)(rw + 12);
        A[4] = *(const float4*)(rw + 16);
        float a20 = rw[20];

#pragma unroll 1
        for (int s = 63; s >= 1; s--) {
            float4 N[5]; float n20 = 0.f;
            if (s > 1) {
                const float* nr = ab + (c * 64 + s - 2) * 24;
                N[0] = *(const float4*)(nr);      N[1] = *(const float4*)(nr + 4);
                N[2] = *(const float4*)(nr + 8);  N[3] = *(const float4*)(nr + 12);
                N[4] = *(const float4*)(nr + 16); n20 = nr[20];
            }
            cur = chase_step(A, a20, Tt[cur]);
            pathbuf[c][x0][s - 1] = (unsigned char)cur;
#pragma unroll
            for (int q = 0; q < 5; q++) A[q] = N[q];
            a20 = n20;
        }
        if (c > 0) {
            const float* er = ab + (c * 64 - 1) * 24;
            float4 E[5];
            E[0] = *(const float4*)(er);      E[1] = *(const float4*)(er + 4);
            E[2] = *(const float4*)(er + 8);  E[3] = *(const float4*)(er + 12);
            E[4] = *(const float4*)(er + 16);
            entry_s[c][x0] = (unsigned char)chase_step(E, er[20], Tt[cur]);
        }
    }
    __syncthreads();

    if (tid == 0) {
        int x = g_lasttag[b];
#pragma unroll
        for (int cc = 7; cc >= 0; cc--) {
            sel[cc] = x;
            x = (cc > 0) ? entry_s[cc][x] : 0;
        }
    }
    __syncthreads();

    for (int t = tid; t < TT; t += 256) {
        int cc = t >> 6;
        out[TAGS_BASE + (size_t)b * TT + t] = (float)pathbuf[cc][sel[cc]][t & 63];
    }
}

extern "C" void kernel_launch(void* const* d_in, const int* in_sizes, int n_in,
                              void* d_out, int out_size)
{
    const float* mlm    = (const float*)d_in[0];
    const int*   gold   = (const int*)  d_in[2];
    const float* W      = (const float*)d_in[3];
    const float* bias   = (const float*)d_in[4];
    const float* trans  = (const float*)d_in[5];
    const float* startT = (const float*)d_in[6];
    const float* endT   = (const float*)d_in[7];
    float* out = (float*)d_out;

    gemm_kernel<<<512, 64>>>(mlm, W, bias, out);
    crf_chain<<<160, 64>>>(out, gold, trans, startT, endT, out);
    crf_fin<<<BB, 256>>>(trans, out);
}

// round 10
// speedup vs baseline: 1.0815x; 1.0815x over previous
#include <cuda_runtime.h>

#define NLAB 21
#define BB   64
#define TT   512
#define DD   1024
#define ROWS (BB*TT)
#define LOGITS_N  (ROWS*NLAB)
#define LOSS_IDX  LOGITS_N
#define TAGS_BASE (LOGITS_N+1)
#define FULLMASK 0xffffffffu
#define NEG_BIG  (-1e30f)

typedef unsigned long long ull;
__device__ __forceinline__ ull fma2(ull a, ull b, ull c) {
    ull d; asm("fma.rn.f32x2 %0, %1, %2, %3;" : "=l"(d) : "l"(a), "l"(b), "l"(c));
    return d;
}
union F4U { float4 f; ull u[2]; };
union F2U { ull u; float2 f; };

// ---------------------------------------------------------------------------
// GEMM: logits = mlm @ W^T + b. 256 blocks x 64 threads, 2 rows/thread
// (tid, tid+64 of a 128-row block). X staged transposed (pitch 129 f4,
// conflict-free), register prefetch of next tile.
// ---------------------------------------------------------------------------
#define GP4 129
__global__ __launch_bounds__(64)
void gemm_kernel(const float* __restrict__ mlm, const float* __restrict__ W,
                 const float* __restrict__ bias, float* out)
{
    __shared__ float4 Xs4[8 * GP4];      // 16512 B
    __shared__ float4 Wq4[NLAB * 8];     // 2688 B
    __shared__ float  bias_s[NLAB];

    const int tid = threadIdx.x;
    const int R0  = blockIdx.x * 128;
    if (blockIdx.x == 0 && tid == 0) out[LOSS_IDX] = 0.0f;
    if (tid < NLAB) bias_s[tid] = bias[tid];

    const int kc  = tid & 7;    // f4 slot within 8-f4 k-tile
    const int rlb = tid >> 3;   // base row 0..7; rows rlb + 8*i

    ull acc0[NLAB], acc1[NLAB];
#pragma unroll
    for (int j = 0; j < NLAB; j++) { acc0[j] = 0ull; acc1[j] = 0ull; }

    const float4* mlm4 = (const float4*)mlm;
    const float4* W4   = (const float4*)W;

    float4 nv[16], nw[3];
#pragma unroll
    for (int i = 0; i < 16; i++)
        nv[i] = mlm4[(size_t)(R0 + rlb + 8 * i) * 256 + kc];
#pragma unroll
    for (int p = 0; p < 3; p++) {
        int w = tid + 64 * p;
        nw[p] = (w < NLAB * 8) ? W4[(w >> 3) * 256 + (w & 7)]
                               : make_float4(0, 0, 0, 0);
    }
#pragma unroll
    for (int i = 0; i < 16; i++) Xs4[kc * GP4 + rlb + 8 * i] = nv[i];
#pragma unroll
    for (int p = 0; p < 3; p++) {
        int w = tid + 64 * p;
        if (w < NLAB * 8) Wq4[w] = nw[p];
    }
    __syncthreads();

#pragma unroll 1
    for (int tile = 0; tile < 32; tile++) {
        if (tile < 31) {
            const int tb = (tile + 1) * 8;
#pragma unroll
            for (int i = 0; i < 16; i++)
                nv[i] = mlm4[(size_t)(R0 + rlb + 8 * i) * 256 + tb + kc];
#pragma unroll
            for (int p = 0; p < 3; p++) {
                int w = tid + 64 * p;
                if (w < NLAB * 8) nw[p] = W4[(w >> 3) * 256 + tb + (w & 7)];
            }
        }
#pragma unroll 2
        for (int kq = 0; kq < 8; kq++) {
            F4U x0, x1;
            x0.f = Xs4[kq * GP4 + tid];
            x1.f = Xs4[kq * GP4 + tid + 64];
#pragma unroll
            for (int j = 0; j < NLAB; j++) {
                F4U w; w.f = Wq4[j * 8 + kq];
                acc0[j] = fma2(x0.u[0], w.u[0], acc0[j]);
                acc0[j] = fma2(x0.u[1], w.u[1], acc0[j]);
                acc1[j] = fma2(x1.u[0], w.u[0], acc1[j]);
                acc1[j] = fma2(x1.u[1], w.u[1], acc1[j]);
            }
        }
        __syncthreads();
        if (tile < 31) {
#pragma unroll
            for (int i = 0; i < 16; i++) Xs4[kc * GP4 + rlb + 8 * i] = nv[i];
#pragma unroll
            for (int p = 0; p < 3; p++) {
                int w = tid + 64 * p;
                if (w < NLAB * 8) Wq4[w] = nw[p];
            }
        }
        __syncthreads();
    }

#pragma unroll
    for (int j = 0; j < NLAB; j++) {
        F2U a;
        a.u = acc0[j];
        out[(size_t)(R0 + tid) * NLAB + j] = a.f.x + a.f.y + bias_s[j];
        a.u = acc1[j];
        out[(size_t)(R0 + tid + 64) * NLAB + j] = a.f.x + a.f.y + bias_s[j];
    }
}

// ---------------------------------------------------------------------------
// argmax_i(row[i] + tr[i]) with lowest-index tie-break
// ---------------------------------------------------------------------------
__device__ __forceinline__ int chase_step(const float* __restrict__ row,
                                          const float* __restrict__ tr)
{
    float v[21];
#pragma unroll
    for (int i = 0; i < 21; i++) v[i] = row[i] + tr[i];
    float m0 = fmaxf(v[0], v[1]),   m1 = fmaxf(v[2], v[3]);
    float m2 = fmaxf(v[4], v[5]),   m3 = fmaxf(v[6], v[7]);
    float m4 = fmaxf(v[8], v[9]),   m5 = fmaxf(v[10], v[11]);
    float m6 = fmaxf(v[12], v[13]), m7 = fmaxf(v[14], v[15]);
    float m8 = fmaxf(v[16], v[17]), m9 = fmaxf(v[18], v[19]);
    float best = fmaxf(fmaxf(fmaxf(fmaxf(m0, m1), fmaxf(m2, m3)),
                             fmaxf(fmaxf(m4, m5), fmaxf(m6, m7))),
                       fmaxf(fmaxf(m8, m9), v[20]));
    int idx = 20;
#pragma unroll
    for (int i = 19; i >= 0; i--) idx = (v[i] == best) ? i : idx;
    return idx;
}

// ---------------------------------------------------------------------------
// CRF: grid 148 x 64, dynamic smem (~119 KB).
//  bid 0-63   forward: preload exp'd emissions, flat barrier-free chain
//  bid 64-127 viterbi: preload raw emissions; w0 chains chunk c while w1
//             chases chunk c-1 backtraces from in-smem alpha history;
//             stitch + tags at end (no g_alpha, no fin kernel)
//  bid 128-147 joint score (batches strided by 40)
// smem floats: em[10752] | abuf[512*32] | Tt[21*24]; then path/entry/sel.
// ---------------------------------------------------------------------------
#define SMEM_SZ 121728
__global__ __launch_bounds__(64)
void crf_all(const float* logits, const int* __restrict__ gold,
             const float* __restrict__ trans, const float* __restrict__ startT,
             const float* __restrict__ endT, float* out)
{
    extern __shared__ float smf[];
    float* em   = smf;                 // 10752 f
    float* abuf = smf + 10752;         // 512*32 = 16384 f
    float* Tt   = smf + 27136;         // 21*24 = 504 f
    unsigned char* path  = (unsigned char*)(smf + 27640);   // 8*21*64
    unsigned char* entry = path + 8 * NLAB * 64;            // 8*21
    int* sel     = (int*)(entry + 168);                     // 8
    int* lasttag = sel + 8;

    const int bid  = blockIdx.x;
    const int tid  = threadIdx.x;
    const int warp = tid >> 5;
    const int lane = tid & 31;
    const int j    = (lane < NLAB) ? lane : (NLAB - 1);

    // ------------------------- joint-score blocks -------------------------
    if (bid >= 128) {
        for (int b = (bid - 128) * 2 + warp; b < BB; b += 40) {
            const float* lg = logits + (size_t)b * TT * NLAB;
            const int*   gb = gold + b * TT;
            float jp = 0.0f;
#pragma unroll 4
            for (int t = lane; t < TT; t += 32) {
                int g = gb[t];
                jp += lg[t * NLAB + g];
                if (t == 0)     jp += startT[g];
                if (t < TT - 1) jp += trans[g * NLAB + gb[t + 1]];
                else            jp += endT[g];
            }
#pragma unroll
            for (int w = 16; w; w >>= 1) jp += __shfl_xor_sync(FULLMASK, jp, w);
            if (lane == 0) atomicAdd(&out[LOSS_IDX], -jp);
        }
        return;
    }

    const bool is_fwd = (bid < 64);
    const int  b      = is_fwd ? bid : (bid - 64);
    const float* lg   = logits + (size_t)b * TT * NLAB;

    // ----------------------------- forward -----------------------------
    if (is_fwd) {
        for (int k = tid; k < TT * NLAB; k += 64) em[k] = __expf(lg[k]);
        __syncthreads();
        if (warp != 0) return;

        float col[NLAB];
#pragma unroll
        for (int i = 0; i < NLAB; i++)
            col[i] = (lane < NLAB) ? __expf(trans[i * NLAB + j]) : 0.0f;

        float st = ((lane < NLAB) ? __expf(startT[j]) : 0.0f) * em[j];
        abuf[lane] = st;
        __syncwarp();
        int eoff = 0;

#pragma unroll 4
        for (int t = 1; t < TT; t++) {
            const float* row = abuf + ((t - 1) & 1) * 32;
            float4 A0 = *(const float4*)(row);
            float4 A1 = *(const float4*)(row + 4);
            float4 A2 = *(const float4*)(row + 8);
            float4 A3 = *(const float4*)(row + 12);
            float4 A4 = *(const float4*)(row + 16);
            float  a20 = row[20];
            float  ev  = em[t * NLAB + j];
            float u0 = A0.x*col[0]  + A1.w*col[7]  + A3.z*col[14];
            float u1 = A0.y*col[1]  + A2.x*col[8]  + A3.w*col[15];
            float u2 = A0.z*col[2]  + A2.y*col[9]  + A4.x*col[16];
            float u3 = A0.w*col[3]  + A2.z*col[10] + A4.y*col[17];
            float u4 = A1.x*col[4]  + A2.w*col[11] + A4.z*col[18];
            float u5 = A1.y*col[5]  + A3.x*col[12] + A4.w*col[19];
            float u6 = A1.z*col[6]  + A3.y*col[13] + a20*col[20];
            float ns = (((u0 + u1) + (u2 + u3)) + ((u4 + u5) + u6)) * ev;
            unsigned eb = __float_as_uint(A0.x) >> 23;   // exact pow2 renorm
            eoff += (int)eb - 127;
            ns *= __uint_as_float((254u - eb) << 23);
            st = ns;
            abuf[(t & 1) * 32 + lane] = ns;
            __syncwarp();
        }

        float val = (lane < NLAB) ? st * __expf(endT[j]) : 0.0f;
#pragma unroll
        for (int w = 16; w; w >>= 1) val += __shfl_xor_sync(FULLMASK, val, w);
        if (lane == 0)
            atomicAdd(&out[LOSS_IDX],
                      (float)eoff * 0.69314718055994531f + __logf(val));
        return;
    }

    // ----------------------------- viterbi -----------------------------
    for (int k = tid; k < TT * NLAB; k += 64) em[k] = lg[k];
    for (int k = tid; k < NLAB * NLAB; k += 64) {
        int i = k / NLAB, x = k - i * NLAB;
        Tt[x * 24 + i] = trans[k];
    }
    __syncthreads();

    float col[NLAB];
    float st = NEG_BIG;
    if (warp == 0) {
#pragma unroll
        for (int i = 0; i < NLAB; i++) col[i] = trans[i * NLAB + j];
    }

    for (int c = 0; c < 9; c++) {
        if (warp == 0 && c < 8) {
            int s0 = 0;
            if (c == 0) {
                st = startT[j] + em[j];
                abuf[lane] = st;
                __syncwarp();
                s0 = 1;
            }
#pragma unroll 4
            for (int s = s0; s < 64; s++) {
                int t = c * 64 + s;
                const float* row = abuf + (t - 1) * 32;
                float4 A0 = *(const float4*)(row);
                float4 A1 = *(const float4*)(row + 4);
                float4 A2 = *(const float4*)(row + 8);
                float4 A3 = *(const float4*)(row + 12);
                float4 A4 = *(const float4*)(row + 16);
                float  a20 = row[20];
                float  ev  = em[t * NLAB + j];
                float v0  = A0.x + col[0],  v1  = A0.y + col[1];
                float v2  = A0.z + col[2],  v3  = A0.w + col[3];
                float v4  = A1.x + col[4],  v5  = A1.y + col[5];
                float v6  = A1.z + col[6],  v7  = A1.w + col[7];
                float v8  = A2.x + col[8],  v9  = A2.y + col[9];
                float v10 = A2.z + col[10], v11 = A2.w + col[11];
                float v12 = A3.x + col[12], v13 = A3.y + col[13];
                float v14 = A3.z + col[14], v15 = A3.w + col[15];
                float v16 = A4.x + col[16], v17 = A4.y + col[17];
                float v18 = A4.z + col[18], v19 = A4.w + col[19];
                float v20 = a20 + col[20];
                float m0 = fmaxf(v0, v1),   m1 = fmaxf(v2, v3);
                float m2 = fmaxf(v4, v5),   m3 = fmaxf(v6, v7);
                float m4 = fmaxf(v8, v9),   m5 = fmaxf(v10, v11);
                float m6 = fmaxf(v12, v13), m7 = fmaxf(v14, v15);
                float m8 = fmaxf(v16, v17), m9 = fmaxf(v18, v19);
                float n0 = fmaxf(m0, m1), n1 = fmaxf(m2, m3);
                float n2 = fmaxf(m4, m5), n3 = fmaxf(m6, m7);
                float n4 = fmaxf(m8, m9);
                st = fmaxf(fmaxf(fmaxf(n0, n1), fmaxf(n2, n3)),
                           fmaxf(n4, v20)) + ev;
                abuf[t * 32 + lane] = st;
                __syncwarp();
            }
        }
        if (warp == 1 && c >= 1 && lane < NLAB) {
            // chase chunk c-1 (alphas for it are complete)
            const int cc = c - 1;
            const int x0 = lane;
            int cur = x0;
            unsigned char* pb = path + (cc * NLAB + x0) * 64;
            pb[63] = (unsigned char)cur;
#pragma unroll 1
            for (int s = 63; s >= 1; s--) {
                const float* row = abuf + (cc * 64 + s - 1) * 32;
                cur = chase_step(row, Tt + cur * 24);
                pb[s - 1] = (unsigned char)cur;
            }
            entry[cc * NLAB + x0] = (cc > 0)
                ? (unsigned char)chase_step(abuf + (cc * 64 - 1) * 32, Tt + cur * 24)
                : (unsigned char)0;
        }
        __syncthreads();
    }

    if (warp == 0) {
        float v = (lane < NLAB) ? (st + endT[j]) : NEG_BIG;
        float m = v;
#pragma unroll
        for (int w = 16; w; w >>= 1) m = fmaxf(m, __shfl_xor_sync(FULLMASK, m, w));
        unsigned bal = __ballot_sync(FULLMASK, v == m);
        if (lane == 0) *lasttag = __ffs(bal) - 1;
    }
    __syncthreads();

    if (tid == 0) {
        int x = *lasttag;
#pragma unroll
        for (int cc = 7; cc >= 0; cc--) {
            sel[cc] = x;
            x = entry[cc * NLAB + x];
        }
    }
    __syncthreads();

    for (int t = tid; t < TT; t += 64) {
        int cc = t >> 6;
        out[TAGS_BASE + (size_t)b * TT + t] =
            (float)path[(cc * NLAB + sel[cc]) * 64 + (t & 63)];
    }
}

extern "C" void kernel_launch(void* const* d_in, const int* in_sizes, int n_in,
                              void* d_out, int out_size)
{
    const float* mlm    = (const float*)d_in[0];
    const int*   gold   = (const int*)  d_in[2];
    const float* W      = (const float*)d_in[3];
    const float* bias   = (const float*)d_in[4];
    const float* trans  = (const float*)d_in[5];
    const float* startT = (const float*)d_in[6];
    const float* endT   = (const float*)d_in[7];
    float* out = (float*)d_out;

    static bool attr_set = false;
    if (!attr_set) {
        cudaFuncSetAttribute(crf_all,
                             cudaFuncAttributeMaxDynamicSharedMemorySize,
                             SMEM_SZ);
        attr_set = true;
    }

    gemm_kernel<<<256, 64>>>(mlm, W, bias, out);
    crf_all<<<148, 64, SMEM_SZ>>>(out, gold, trans, startT, endT, out);
}

// round 11
// speedup vs baseline: 1.3543x; 1.2522x over previous
#include <cuda_runtime.h>

#define NLAB 21
#define BB   64
#define TT   512
#define DD   1024
#define ROWS (BB*TT)
#define LOGITS_N  (ROWS*NLAB)
#define LOSS_IDX  LOGITS_N
#define TAGS_BASE (LOGITS_N+1)
#define FULLMASK 0xffffffffu
#define NEG_BIG  (-1e30f)

typedef unsigned long long ull;
__device__ __forceinline__ ull fma2(ull a, ull b, ull c) {
    ull d; asm("fma.rn.f32x2 %0, %1, %2, %3;" : "=l"(d) : "l"(a), "l"(b), "l"(c));
    return d;
}
union F4U { float4 f; ull u[2]; };
union F2U { ull u; float2 f; };

// ---------------------------------------------------------------------------
// GEMM: logits = mlm @ W^T + b. 256 blocks x 128 threads.
// thread = (2 rows: rs, rs+64) x (one 512-float K-half). Split-K combine via
// smem. X staged transposed per tile (16 f4-planes, pitch 129), reg prefetch.
// ---------------------------------------------------------------------------
#define GP4 129
__global__ __launch_bounds__(128)
void gemm_kernel(const float* __restrict__ mlm, const float* __restrict__ W,
                 const float* __restrict__ bias, float* out)
{
    __shared__ float4 Xs4[16 * GP4];       // 33024 B
    __shared__ float4 Wq4[2][NLAB * 8];    // 5376 B
    __shared__ float  bias_s[NLAB];

    const int tid  = threadIdx.x;
    const int half = tid >> 6;
    const int rs   = tid & 63;
    const int R0   = blockIdx.x * 128;
    const int row0 = R0 + rs;
    const int row1 = R0 + rs + 64;

    if (blockIdx.x == 0 && tid == 0) out[LOSS_IDX] = 0.0f;
    if (tid < NLAB) bias_s[tid] = bias[tid];

    ull acc0[NLAB], acc1[NLAB];
#pragma unroll
    for (int j = 0; j < NLAB; j++) { acc0[j] = 0ull; acc1[j] = 0ull; }

    const float4* mlm4 = (const float4*)mlm;
    const float4* W4   = (const float4*)W;

    // staging geometry
    const int kc = tid & 15;          // f4 slot in combined 16-wide tile
    const int rb = tid >> 4;          // base row 0..7, rows rb + 8*i

    float4 nv[16], nw[3];
    // preload tile 0
#pragma unroll
    for (int i = 0; i < 16; i++) {
        int fk = (kc < 8) ? kc : (120 + kc);
        nv[i] = mlm4[(size_t)(R0 + rb + 8 * i) * 256 + fk];
    }
#pragma unroll
    for (int p = 0; p < 3; p++) {
        int idx = tid + 128 * p;
        if (idx < 336) {
            int h = idx >= 168;
            int q = idx - h * 168;
            nw[p] = W4[(q >> 3) * 256 + h * 128 + (q & 7)];
        }
    }
#pragma unroll
    for (int i = 0; i < 16; i++) Xs4[kc * GP4 + rb + 8 * i] = nv[i];
#pragma unroll
    for (int p = 0; p < 3; p++) {
        int idx = tid + 128 * p;
        if (idx < 336) {
            int h = idx >= 168;
            Wq4[h][idx - h * 168] = nw[p];
        }
    }
    __syncthreads();

#pragma unroll 1
    for (int tile = 0; tile < 16; tile++) {
        if (tile < 15) {
            const int tb = (tile + 1) * 8;
#pragma unroll
            for (int i = 0; i < 16; i++) {
                int fk = (kc < 8) ? (tb + kc) : (120 + tb + kc);
                nv[i] = mlm4[(size_t)(R0 + rb + 8 * i) * 256 + fk];
            }
#pragma unroll
            for (int p = 0; p < 3; p++) {
                int idx = tid + 128 * p;
                if (idx < 336) {
                    int h = idx >= 168;
                    int q = idx - h * 168;
                    nw[p] = W4[(q >> 3) * 256 + h * 128 + tb + (q & 7)];
                }
            }
        }
#pragma unroll 2
        for (int kq = 0; kq < 8; kq++) {
            F4U x0, x1;
            x0.f = Xs4[(half * 8 + kq) * GP4 + rs];
            x1.f = Xs4[(half * 8 + kq) * GP4 + rs + 64];
#pragma unroll
            for (int j = 0; j < NLAB; j++) {
                F4U w; w.f = Wq4[half][j * 8 + kq];
                acc0[j] = fma2(x0.u[0], w.u[0], acc0[j]);
                acc0[j] = fma2(x0.u[1], w.u[1], acc0[j]);
                acc1[j] = fma2(x1.u[0], w.u[0], acc1[j]);
                acc1[j] = fma2(x1.u[1], w.u[1], acc1[j]);
            }
        }
        __syncthreads();
        if (tile < 15) {
#pragma unroll
            for (int i = 0; i < 16; i++) Xs4[kc * GP4 + rb + 8 * i] = nv[i];
#pragma unroll
            for (int p = 0; p < 3; p++) {
                int idx = tid + 128 * p;
                if (idx < 336) {
                    int h = idx >= 168;
                    Wq4[h][idx - h * 168] = nw[p];
                }
            }
            __syncthreads();
        }
    }

    // split-K combine
    __syncthreads();
    float* sred = (float*)Xs4;   // 64 x 42 floats
    if (half == 1) {
#pragma unroll
        for (int j = 0; j < NLAB; j++) {
            F2U a;
            a.u = acc0[j]; sred[rs * 42 + j]        = a.f.x + a.f.y;
            a.u = acc1[j]; sred[rs * 42 + NLAB + j] = a.f.x + a.f.y;
        }
    }
    __syncthreads();
    if (half == 0) {
#pragma unroll
        for (int j = 0; j < NLAB; j++) {
            F2U a;
            a.u = acc0[j];
            out[(size_t)row0 * NLAB + j] =
                a.f.x + a.f.y + sred[rs * 42 + j] + bias_s[j];
            a.u = acc1[j];
            out[(size_t)row1 * NLAB + j] =
                a.f.x + a.f.y + sred[rs * 42 + NLAB + j] + bias_s[j];
        }
    }
}

// ---------------------------------------------------------------------------
// argmax_k(row[k] + tr[k]), lowest index wins
// ---------------------------------------------------------------------------
__device__ __forceinline__ int chase_step(const float* __restrict__ row,
                                          const float* __restrict__ tr)
{
    float4 A0 = *(const float4*)(row),     B0 = *(const float4*)(tr);
    float4 A1 = *(const float4*)(row + 4), B1 = *(const float4*)(tr + 4);
    float4 A2 = *(const float4*)(row + 8), B2 = *(const float4*)(tr + 8);
    float4 A3 = *(const float4*)(row + 12),B3 = *(const float4*)(tr + 12);
    float4 A4 = *(const float4*)(row + 16),B4 = *(const float4*)(tr + 16);
    float v[21];
    v[0]=A0.x+B0.x; v[1]=A0.y+B0.y; v[2]=A0.z+B0.z; v[3]=A0.w+B0.w;
    v[4]=A1.x+B1.x; v[5]=A1.y+B1.y; v[6]=A1.z+B1.z; v[7]=A1.w+B1.w;
    v[8]=A2.x+B2.x; v[9]=A2.y+B2.y; v[10]=A2.z+B2.z; v[11]=A2.w+B2.w;
    v[12]=A3.x+B3.x; v[13]=A3.y+B3.y; v[14]=A3.z+B3.z; v[15]=A3.w+B3.w;
    v[16]=A4.x+B4.x; v[17]=A4.y+B4.y; v[18]=A4.z+B4.z; v[19]=A4.w+B4.w;
    v[20]=row[20]+tr[20];
    float m0 = fmaxf(v[0], v[1]),   m1 = fmaxf(v[2], v[3]);
    float m2 = fmaxf(v[4], v[5]),   m3 = fmaxf(v[6], v[7]);
    float m4 = fmaxf(v[8], v[9]),   m5 = fmaxf(v[10], v[11]);
    float m6 = fmaxf(v[12], v[13]), m7 = fmaxf(v[14], v[15]);
    float m8 = fmaxf(v[16], v[17]), m9 = fmaxf(v[18], v[19]);
    float best = fmaxf(fmaxf(fmaxf(fmaxf(m0, m1), fmaxf(m2, m3)),
                             fmaxf(fmaxf(m4, m5), fmaxf(m6, m7))),
                       fmaxf(fmaxf(m8, m9), v[20]));
    int idx = 20;
#pragma unroll
    for (int i = 19; i >= 0; i--) idx = (v[i] == best) ? i : idx;
    return idx;
}

// ---------------------------------------------------------------------------
// CRF: grid 148 x 128.
//  bid 0-63   forward:  w0 left chain (t 0..255), w1 right chain (511..256),
//             combine Z = sum_j (E^T alpha)_j * rb256_j.
//  bid 64-127 viterbi:  w0 left alpha chain, w1 right d-chain, w2 left chases,
//             w3 right chases (both lag one 64-chunk), junction + stitch.
//  bid 128-147 joint score.
// ---------------------------------------------------------------------------
#define SMEM_SZ 124416
__global__ __launch_bounds__(128)
void crf_all(const float* logits, const int* __restrict__ gold,
             const float* __restrict__ trans, const float* __restrict__ startT,
             const float* __restrict__ endT, float* out)
{
    extern __shared__ float smf[];
    float* em  = smf;                  // 10752
    float* ab  = smf + 10752;          // 512 rows x 32
    float* Ts  = smf + 27136;          // 21 x 24 (plain)
    float* Tt  = smf + 27640;          // 21 x 24 (transposed)
    float* rbf = smf + 28144;          // 32
    float* dbl = smf + 28176;          // 4 x 32 (fwd double buffers)
    unsigned char* path  = (unsigned char*)(smf + 28304);   // 8*21*64
    unsigned char* entry = path + 8 * NLAB * 64;            // 8*21
    int* sel    = (int*)(entry + 168);
    int* lastp  = sel + 8;
    int* eoffRp = sel + 9;

    const int bid  = blockIdx.x;
    const int tid  = threadIdx.x;
    const int warp = tid >> 5;
    const int lane = tid & 31;
    const int j    = (lane < NLAB) ? lane : (NLAB - 1);

    // ------------------------- joint-score blocks -------------------------
    if (bid >= 128) {
        const int b = (bid - 128) * 4 + warp;
        if (b < BB) {
            const float* lg = logits + (size_t)b * TT * NLAB;
            const int*   gb = gold + b * TT;
            float jp = 0.0f;
#pragma unroll 4
            for (int t = lane; t < TT; t += 32) {
                int g = gb[t];
                jp += lg[t * NLAB + g];
                if (t == 0)     jp += startT[g];
                if (t < TT - 1) jp += trans[g * NLAB + gb[t + 1]];
                else            jp += endT[g];
            }
#pragma unroll
            for (int w = 16; w; w >>= 1) jp += __shfl_xor_sync(FULLMASK, jp, w);
            if (lane == 0) atomicAdd(&out[LOSS_IDX], -jp);
        }
        return;
    }

    const bool is_fwd = (bid < 64);
    const int  b      = is_fwd ? bid : (bid - 64);
    const float* lg   = logits + (size_t)b * TT * NLAB;

    // ------------------------------- forward ------------------------------
    if (is_fwd) {
        for (int k = tid; k < TT * NLAB; k += 128) em[k] = __expf(lg[k]);
        __syncthreads();

        int eo = 0;
        float col[NLAB];
        if (warp == 0) {   // left chain
#pragma unroll
            for (int i = 0; i < NLAB; i++)
                col[i] = (lane < NLAB) ? __expf(trans[i * NLAB + j]) : 0.0f;
            float* mb = dbl;
            float st = ((lane < NLAB) ? __expf(startT[j]) : 0.0f) * em[j];
            mb[lane] = st;
            __syncwarp();
#pragma unroll 4
            for (int t = 1; t <= 255; t++) {
                const float* row = mb + ((t - 1) & 1) * 32;
                float4 A0 = *(const float4*)(row);
                float4 A1 = *(const float4*)(row + 4);
                float4 A2 = *(const float4*)(row + 8);
                float4 A3 = *(const float4*)(row + 12);
                float4 A4 = *(const float4*)(row + 16);
                float  a20 = row[20];
                float  ev  = em[t * NLAB + j];
                float u0 = A0.x*col[0]  + A1.w*col[7]  + A3.z*col[14];
                float u1 = A0.y*col[1]  + A2.x*col[8]  + A3.w*col[15];
                float u2 = A0.z*col[2]  + A2.y*col[9]  + A4.x*col[16];
                float u3 = A0.w*col[3]  + A2.z*col[10] + A4.y*col[17];
                float u4 = A1.x*col[4]  + A2.w*col[11] + A4.z*col[18];
                float u5 = A1.y*col[5]  + A3.x*col[12] + A4.w*col[19];
                float u6 = A1.z*col[6]  + A3.y*col[13] + a20*col[20];
                float ns = (((u0 + u1) + (u2 + u3)) + ((u4 + u5) + u6)) * ev;
                unsigned eb = __float_as_uint(A0.x) >> 23;
                eo += (int)eb - 127;
                ns *= __uint_as_float((254u - eb) << 23);
                mb[(t & 1) * 32 + lane] = ns;
                __syncwarp();
            }
        } else if (warp == 1) {   // right chain
#pragma unroll
            for (int i = 0; i < NLAB; i++)
                col[i] = (lane < NLAB) ? __expf(trans[j * NLAB + i]) : 0.0f;
            float* mb = dbl + 64;
            float st = (lane < NLAB)
                ? em[511 * NLAB + j] * __expf(endT[j]) : 0.0f;
            mb[32 + lane] = st;   // slot 1 (t=511)
            __syncwarp();
#pragma unroll 4
            for (int t = 510; t >= 256; t--) {
                const float* row = mb + (((t + 1) & 1)) * 32;
                float4 A0 = *(const float4*)(row);
                float4 A1 = *(const float4*)(row + 4);
                float4 A2 = *(const float4*)(row + 8);
                float4 A3 = *(const float4*)(row + 12);
                float4 A4 = *(const float4*)(row + 16);
                float  a20 = row[20];
                float  ev  = em[t * NLAB + j];
                float u0 = A0.x*col[0]  + A1.w*col[7]  + A3.z*col[14];
                float u1 = A0.y*col[1]  + A2.x*col[8]  + A3.w*col[15];
                float u2 = A0.z*col[2]  + A2.y*col[9]  + A4.x*col[16];
                float u3 = A0.w*col[3]  + A2.z*col[10] + A4.y*col[17];
                float u4 = A1.x*col[4]  + A2.w*col[11] + A4.z*col[18];
                float u5 = A1.y*col[5]  + A3.x*col[12] + A4.w*col[19];
                float u6 = A1.z*col[6]  + A3.y*col[13] + a20*col[20];
                float ns = (((u0 + u1) + (u2 + u3)) + ((u4 + u5) + u6)) * ev;
                unsigned eb = __float_as_uint(A0.x) >> 23;
                eo += (int)eb - 127;
                ns *= __uint_as_float((254u - eb) << 23);
                st = ns;
                mb[(t & 1) * 32 + lane] = ns;
                __syncwarp();
            }
            rbf[lane] = st;       // rb_256 (lanes >= 21 are 0)
            if (lane == 0) *eoffRp = eo;
        }
        __syncthreads();

        if (warp == 0) {   // combine: Z = sum_j (E^T alpha255)_j * rb256_j
            const float* row = dbl + 32;   // alpha255 (slot 1)
            float4 A0 = *(const float4*)(row);
            float4 A1 = *(const float4*)(row + 4);
            float4 A2 = *(const float4*)(row + 8);
            float4 A3 = *(const float4*)(row + 12);
            float4 A4 = *(const float4*)(row + 16);
            float  a20 = row[20];
            float u0 = A0.x*col[0]  + A1.w*col[7]  + A3.z*col[14];
            float u1 = A0.y*col[1]  + A2.x*col[8]  + A3.w*col[15];
            float u2 = A0.z*col[2]  + A2.y*col[9]  + A4.x*col[16];
            float u3 = A0.w*col[3]  + A2.z*col[10] + A4.y*col[17];
            float u4 = A1.x*col[4]  + A2.w*col[11] + A4.z*col[18];
            float u5 = A1.y*col[5]  + A3.x*col[12] + A4.w*col[19];
            float u6 = A1.z*col[6]  + A3.y*col[13] + a20*col[20];
            float u  = (((u0 + u1) + (u2 + u3)) + ((u4 + u5) + u6));
            float val = (lane < NLAB) ? u * rbf[lane] : 0.0f;
#pragma unroll
            for (int w = 16; w; w >>= 1) val += __shfl_xor_sync(FULLMASK, val, w);
            if (lane == 0)
                atomicAdd(&out[LOSS_IDX],
                          (float)(eo + *eoffRp) * 0.69314718055994531f +
                          __logf(val));
        }
        return;
    }

    // ------------------------------- viterbi ------------------------------
    for (int k = tid; k < TT * NLAB; k += 128) em[k] = lg[k];
    for (int k = tid; k < NLAB * NLAB; k += 128) {
        int i = k / NLAB, x = k - i * NLAB;
        Ts[i * 24 + x] = trans[k];
        Tt[x * 24 + i] = trans[k];
    }
    __syncthreads();

    float col[NLAB];
    if (warp == 0) {
#pragma unroll
        for (int i = 0; i < NLAB; i++) col[i] = trans[i * NLAB + j];
    } else if (warp == 1) {
#pragma unroll
        for (int i = 0; i < NLAB; i++) col[i] = trans[j * NLAB + i];
    }

    for (int it = 0; it < 5; it++) {
        if (warp == 0 && it < 4) {            // left alpha chain, chunk it
            int t = it * 64;
            if (it == 0) {
                ab[lane] = startT[j] + em[j];
                __syncwarp();
                t = 1;
            }
            const int t1 = it * 64 + 63;
#pragma unroll 4
            for (; t <= t1; t++) {
                const float* row = ab + (t - 1) * 32;
                float4 A0 = *(const float4*)(row);
                float4 A1 = *(const float4*)(row + 4);
                float4 A2 = *(const float4*)(row + 8);
                float4 A3 = *(const float4*)(row + 12);
                float4 A4 = *(const float4*)(row + 16);
                float  a20 = row[20];
                float v0  = A0.x + col[0],  v1  = A0.y + col[1];
                float v2  = A0.z + col[2],  v3  = A0.w + col[3];
                float v4  = A1.x + col[4],  v5  = A1.y + col[5];
                float v6  = A1.z + col[6],  v7  = A1.w + col[7];
                float v8  = A2.x + col[8],  v9  = A2.y + col[9];
                float v10 = A2.z + col[10], v11 = A2.w + col[11];
                float v12 = A3.x + col[12], v13 = A3.y + col[13];
                float v14 = A3.z + col[14], v15 = A3.w + col[15];
                float v16 = A4.x + col[16], v17 = A4.y + col[17];
                float v18 = A4.z + col[18], v19 = A4.w + col[19];
                float v20 = a20 + col[20];
                float m0 = fmaxf(v0, v1),   m1 = fmaxf(v2, v3);
                float m2 = fmaxf(v4, v5),   m3 = fmaxf(v6, v7);
                float m4 = fmaxf(v8, v9),   m5 = fmaxf(v10, v11);
                float m6 = fmaxf(v12, v13), m7 = fmaxf(v14, v15);
                float m8 = fmaxf(v16, v17), m9 = fmaxf(v18, v19);
                float best = fmaxf(fmaxf(fmaxf(fmaxf(m0, m1), fmaxf(m2, m3)),
                                         fmaxf(fmaxf(m4, m5), fmaxf(m6, m7))),
                                   fmaxf(fmaxf(m8, m9), v20));
                ab[t * 32 + lane] = best + em[t * NLAB + j];
                __syncwarp();
            }
        }
        if (warp == 1 && it < 4) {            // right d chain
            int hi = (it == 0) ? 510 : (511 - 64 * it);
            int lo = 448 - 64 * it;
            if (it == 0) {
                ab[511 * 32 + lane] = em[511 * NLAB + j] + endT[j];
                __syncwarp();
            }
#pragma unroll 4
            for (int t = hi; t >= lo; t--) {
                const float* row = ab + (t + 1) * 32;
                float4 A0 = *(const float4*)(row);
                float4 A1 = *(const float4*)(row + 4);
                float4 A2 = *(const float4*)(row + 8);
                float4 A3 = *(const float4*)(row + 12);
                float4 A4 = *(const float4*)(row + 16);
                float  a20 = row[20];
                float v0  = A0.x + col[0],  v1  = A0.y + col[1];
                float v2  = A0.z + col[2],  v3  = A0.w + col[3];
                float v4  = A1.x + col[4],  v5  = A1.y + col[5];
                float v6  = A1.z + col[6],  v7  = A1.w + col[7];
                float v8  = A2.x + col[8],  v9  = A2.y + col[9];
                float v10 = A2.z + col[10], v11 = A2.w + col[11];
                float v12 = A3.x + col[12], v13 = A3.y + col[13];
                float v14 = A3.z + col[14], v15 = A3.w + col[15];
                float v16 = A4.x + col[16], v17 = A4.y + col[17];
                float v18 = A4.z + col[18], v19 = A4.w + col[19];
                float v20 = a20 + col[20];
                float m0 = fmaxf(v0, v1),   m1 = fmaxf(v2, v3);
                float m2 = fmaxf(v4, v5),   m3 = fmaxf(v6, v7);
                float m4 = fmaxf(v8, v9),   m5 = fmaxf(v10, v11);
                float m6 = fmaxf(v12, v13), m7 = fmaxf(v14, v15);
                float m8 = fmaxf(v16, v17), m9 = fmaxf(v18, v19);
                float best = fmaxf(fmaxf(fmaxf(fmaxf(m0, m1), fmaxf(m2, m3)),
                                         fmaxf(fmaxf(m4, m5), fmaxf(m6, m7))),
                                   fmaxf(fmaxf(m8, m9), v20));
                ab[t * 32 + lane] = best + em[t * NLAB + j];
                __syncwarp();
            }
        }
        if (warp == 2 && it >= 1 && lane < NLAB) {   // left chase, chunk it-1
            const int cc = it - 1;
            const int x0 = lane;
            int cur = x0;
            unsigned char* pb = path + (cc * NLAB + x0) * 64;
            pb[63] = (unsigned char)cur;
#pragma unroll 1
            for (int s = 63; s >= 1; s--) {
                cur = chase_step(ab + (cc * 64 + s - 1) * 32, Tt + cur * 24);
                pb[s - 1] = (unsigned char)cur;
            }
            entry[cc * NLAB + x0] = (cc > 0)
                ? (unsigned char)chase_step(ab + (cc * 64 - 1) * 32, Tt + cur * 24)
                : (unsigned char)0;
        }
        if (warp == 3 && it >= 1 && lane < NLAB) {   // right chase, chunk 8-it
            const int rc = 8 - it;
            const int x0 = lane;   // tag at t = 64*rc - 1
            int cur = x0;
            unsigned char* pb = path + (rc * NLAB + x0) * 64;
#pragma unroll 1
            for (int s = 0; s < 64; s++) {
                cur = chase_step(ab + (rc * 64 + s) * 32, Ts + cur * 24);
                pb[s] = (unsigned char)cur;
            }
        }
        __syncthreads();
    }

    // junction: y255 = argmax_j(alpha255[j] + max_k(Ts[j][k] + d256[k]))
    if (warp == 0) {
        float tot = NEG_BIG;
        if (lane < NLAB) {
            const float* dr = ab + 256 * 32;
            const float* tr = Ts + j * 24;
            float v[21];
#pragma unroll
            for (int i = 0; i < 21; i++) v[i] = dr[i] + tr[i];
            float m0 = fmaxf(v[0], v[1]),   m1 = fmaxf(v[2], v[3]);
            float m2 = fmaxf(v[4], v[5]),   m3 = fmaxf(v[6], v[7]);
            float m4 = fmaxf(v[8], v[9]),   m5 = fmaxf(v[10], v[11]);
            float m6 = fmaxf(v[12], v[13]), m7 = fmaxf(v[14], v[15]);
            float m8 = fmaxf(v[16], v[17]), m9 = fmaxf(v[18], v[19]);
            float vb = fmaxf(fmaxf(fmaxf(fmaxf(m0, m1), fmaxf(m2, m3)),
                                   fmaxf(fmaxf(m4, m5), fmaxf(m6, m7))),
                             fmaxf(fmaxf(m8, m9), v[20]));
            tot = ab[255 * 32 + j] + vb;
        }
        float m = tot;
#pragma unroll
        for (int w = 16; w; w >>= 1) m = fmaxf(m, __shfl_xor_sync(FULLMASK, m, w));
        unsigned bal = __ballot_sync(FULLMASK, tot == m);
        if (lane == 0) *lastp = __ffs(bal) - 1;
    }
    __syncthreads();

    if (tid == 0) {
        int x = *lastp;
        for (int cc = 3; cc >= 0; cc--) { sel[cc] = x; x = entry[cc * NLAB + x]; }
        x = *lastp;
        for (int cc = 4; cc <= 7; cc++) {
            sel[cc] = x;
            x = path[(cc * NLAB + x) * 64 + 63];
        }
    }
    __syncthreads();

    for (int t = tid; t < TT; t += 128) {
        int cc = t >> 6;
        out[TAGS_BASE + (size_t)b * TT + t] =
            (float)path[(cc * NLAB + sel[cc]) * 64 + (t & 63)];
    }
}

extern "C" void kernel_launch(void* const* d_in, const int* in_sizes, int n_in,
                              void* d_out, int out_size)
{
    const float* mlm    = (const float*)d_in[0];
    const int*   gold   = (const int*)  d_in[2];
    const float* W      = (const float*)d_in[3];
    const float* bias   = (const float*)d_in[4];
    const float* trans  = (const float*)d_in[5];
    const float* startT = (const float*)d_in[6];
    const float* endT   = (const float*)d_in[7];
    float* out = (float*)d_out;

    cudaFuncSetAttribute(crf_all,
                         cudaFuncAttributeMaxDynamicSharedMemorySize, SMEM_SZ);

    gemm_kernel<<<256, 128>>>(mlm, W, bias, out);
    crf_all<<<148, 128, SMEM_SZ>>>(out, gold, trans, startT, endT, out);
}